// round 3
// baseline (speedup 1.0000x reference)
#include <cuda_runtime.h>
#include <cuda_bf16.h>
#include <math.h>

// ---------------- problem constants ----------------
#define NBANDS 5
#define BGRAPH 512
#define NPG    62
#define NTOT   (BGRAPH*NPG)     // 31744
#define FIN    5
#define HEADS  8
#define CCH    3
#define HC     (HEADS*CCH)      // 24
#define EG     992
#define ETOT   (BGRAPH*EG)      // 507904
#define DEDIM  930

// ---------------- device scratch (no allocs allowed) ----------------
__device__ float g_bnsum[NBANDS][FIN];
__device__ float g_bnsq [NBANDS][FIN];
__device__ float g_scale[NBANDS][FIN];
__device__ float g_shift[NBANDS][FIN];
__device__ float g_pooled[NBANDS][BGRAPH][CCH];
__device__ float g_den[BGRAPH][DEDIM];
__device__ float g_Q[BGRAPH][64];
__device__ float g_K[BGRAPH][64];
__device__ float g_V[BGRAPH][64];

// ---------------- kernel 0: zero BN accumulators ----------------
__global__ void zero_stats_kernel() {
    int t = threadIdx.x;
    if (t < NBANDS*FIN) {
        ((float*)g_bnsum)[t] = 0.f;
        ((float*)g_bnsq )[t] = 0.f;
    }
}

// ---------------- kernel 1: BN partial sums ----------------
__global__ __launch_bounds__(256) void bn_partial_kernel(const float* __restrict__ x) {
    int band = blockIdx.y;
    const float* xb = x + (size_t)band * NTOT * FIN;
    float s[FIN], q[FIN];
#pragma unroll
    for (int f = 0; f < FIN; f++) { s[f] = 0.f; q[f] = 0.f; }
    for (int n = blockIdx.x * blockDim.x + threadIdx.x; n < NTOT; n += gridDim.x * blockDim.x) {
#pragma unroll
        for (int f = 0; f < FIN; f++) {
            float v = xb[n*FIN + f];
            s[f] += v; q[f] += v*v;
        }
    }
#pragma unroll
    for (int f = 0; f < FIN; f++) {
#pragma unroll
        for (int o = 16; o; o >>= 1) {
            s[f] += __shfl_xor_sync(0xffffffffu, s[f], o);
            q[f] += __shfl_xor_sync(0xffffffffu, q[f], o);
        }
    }
    __shared__ float rs[8][FIN], rq[8][FIN];
    int w = threadIdx.x >> 5, lane = threadIdx.x & 31;
    if (lane == 0) {
#pragma unroll
        for (int f = 0; f < FIN; f++) { rs[w][f] = s[f]; rq[w][f] = q[f]; }
    }
    __syncthreads();
    if (threadIdx.x < FIN) {
        int f = threadIdx.x;
        float S = 0.f, Q = 0.f;
#pragma unroll
        for (int ww = 0; ww < 8; ww++) { S += rs[ww][f]; Q += rq[ww][f]; }
        atomicAdd(&g_bnsum[band][f], S);
        atomicAdd(&g_bnsq [band][f], Q);
    }
}

// ---------------- kernel 2: finalize BN scale/shift ----------------
__global__ void bn_finalize_kernel(const float* __restrict__ gamma,
                                   const float* __restrict__ beta) {
    int t = threadIdx.x;
    if (t < NBANDS*FIN) {
        int band = t / FIN, f = t % FIN;
        float mu  = g_bnsum[band][f] * (1.f / NTOT);
        float var = g_bnsq [band][f] * (1.f / NTOT) - mu*mu;
        float sc  = gamma[t] * rsqrtf(var + 1e-5f);
        g_scale[band][f] = sc;
        g_shift[band][f] = beta[t] - mu*sc;
    }
}

// ---------------- kernel 3: per-(band,graph) GAT + pool ----------------
// 512 threads. Fused float4 node state: (xt0, xt1, xt2, al_src).
__global__ __launch_bounds__(512) void gat_kernel(
    const float* __restrict__ x, const int* __restrict__ ei,
    const float* __restrict__ W, const float* __restrict__ asrc,
    const float* __restrict__ adst, const float* __restrict__ gbias)
{
    int g = blockIdx.x, band = blockIdx.y;
    __shared__ float  sW[FIN*HC];
    __shared__ float  sAS[HC], sAD[HC];
    __shared__ float  sSc[FIN], sSh[FIN], sBias[CCH];
    __shared__ float  sXN[NPG*FIN];
    __shared__ float4 sXT4[NPG*HEADS];      // (xt0,xt1,xt2,al_src)
    __shared__ float  sALD[NPG*HEADS];
    __shared__ int    sCnt[NPG];
    __shared__ int    sOff[NPG+1];
    __shared__ int    sPos[NPG];
    __shared__ int    sCsr[NPG + EG];
    __shared__ float  sOut[NPG*HC];
    __shared__ float  sPool[CCH];

    int tid = threadIdx.x;
    // ---- stage params (disjoint ranges) + load my edges into registers ----
    const int* e0 = ei + ((size_t)band*2 + 0)*ETOT + (size_t)g*EG;
    const int* e1 = ei + ((size_t)band*2 + 1)*ETOT + (size_t)g*EG;
    int gbase = g * NPG;
    int myS0 = e0[tid] - gbase;             // tid < 512 <= EG always valid
    int myD0 = e1[tid] - gbase;
    int myS1 = 0, myD1 = -1;
    if (tid + 512 < EG) {
        myS1 = e0[tid + 512] - gbase;
        myD1 = e1[tid + 512] - gbase;
    }

    if (tid < FIN*HC)                   sW[tid]       = W[band*FIN*HC + tid];
    if (tid >= 128 && tid < 128+HC)     sAS[tid-128]  = asrc[band*HC + (tid-128)];
    if (tid >= 160 && tid < 160+HC)     sAD[tid-160]  = adst[band*HC + (tid-160)];
    if (tid >= 192 && tid < 192+FIN)    sSc[tid-192]  = g_scale[band][tid-192];
    if (tid >= 200 && tid < 200+FIN)    sSh[tid-200]  = g_shift[band][tid-200];
    if (tid >= 208 && tid < 208+CCH)    sBias[tid-208]= gbias[band*CCH + (tid-208)];
    if (tid >= 256 && tid < 256+NPG)    sCnt[tid-256] = 1;   // self-loop seed
    if (tid < CCH) sPool[tid] = 0.f;

    // node features (BN applied): 310 elems — needs sSc/sSh, so sync first
    __syncthreads();
    const float* xg = x + ((size_t)band * NTOT + (size_t)g * NPG) * FIN;
    if (tid < NPG*FIN) {
        int f = tid % FIN;
        sXN[tid] = xg[tid] * sSc[f] + sSh[f];
    }
    // count in-degree while sXN settles (sCnt ready after previous sync)
    atomicAdd(&sCnt[myD0], 1);
    if (myD1 >= 0) atomicAdd(&sCnt[myD1], 1);
    __syncthreads();

    // fused projection + logits: item (n,h) -> float4 + ald   (496 items)
    if (tid < NPG*HEADS) {
        int n = tid >> 3, h = tid & 7;
        float x0 = 0.f, x1 = 0.f, x2 = 0.f;
#pragma unroll
        for (int f = 0; f < FIN; f++) {
            float xv = sXN[n*FIN + f];
            x0 += xv * sW[f*HC + h*CCH + 0];
            x1 += xv * sW[f*HC + h*CCH + 1];
            x2 += xv * sW[f*HC + h*CCH + 2];
        }
        float as = x0*sAS[h*CCH+0] + x1*sAS[h*CCH+1] + x2*sAS[h*CCH+2];
        float ad = x0*sAD[h*CCH+0] + x1*sAD[h*CCH+1] + x2*sAD[h*CCH+2];
        sXT4[tid] = make_float4(x0, x1, x2, as);
        sALD[tid] = ad;
    }
    // prefix scan of counts in warp 0 (lane i handles i and i+32)
    if (tid < 32) {
        int lane = tid;
        int c0 = sCnt[lane];
        int c1 = (lane + 32 < NPG) ? sCnt[lane + 32] : 0;
        int cnt0 = c0, cnt1 = c1;
#pragma unroll
        for (int o = 1; o < 32; o <<= 1) {
            int t = __shfl_up_sync(0xffffffffu, c0, o);
            if (lane >= o) c0 += t;
        }
        int tot0 = __shfl_sync(0xffffffffu, c0, 31);
#pragma unroll
        for (int o = 1; o < 32; o <<= 1) {
            int t = __shfl_up_sync(0xffffffffu, c1, o);
            if (lane >= o) c1 += t;
        }
        c1 += tot0;
        sOff[lane] = c0 - cnt0;                        // exclusive
        if (lane + 32 < NPG) sOff[lane + 32] = c1 - cnt1;
        if (lane == 31) sOff[NPG] = c1;                // total = EG + NPG
    }
    __syncthreads();
    if (tid < NPG) { sCsr[sOff[tid]] = tid; sPos[tid] = sOff[tid] + 1; }
    __syncthreads();
    {
        int p = atomicAdd(&sPos[myD0], 1);
        sCsr[p] = myS0;
        if (myD1 >= 0) {
            int p1 = atomicAdd(&sPos[myD1], 1);
            sCsr[p1] = myS1;
        }
    }
    __syncthreads();

    // dst-major softmax aggregation: one thread per (dst, head) item (496)
    if (tid < NPG*HEADS) {
        int d = tid % NPG, h = tid / NPG;   // spread d across threads
        float ald = sALD[d*HEADS + h];
        float den = 0.f, a0 = 0.f, a1 = 0.f, a2 = 0.f;
        int k0 = sOff[d], k1 = sOff[d+1];
        for (int k = k0; k < k1; k++) {
            int s = sCsr[k];
            float4 v = sXT4[s*HEADS + h];
            float al = v.w + ald;
            float ev = al > 0.f ? al : 0.2f * al;   // leaky_relu(0.2)
            float ex = __expf(ev);                  // logits are O(1): no max needed
            den += ex;
            a0 += ex * v.x; a1 += ex * v.y; a2 += ex * v.z;
        }
        float inv = 1.f / den;
        sOut[d*HC + h*CCH + 0] = a0 * inv;
        sOut[d*HC + h*CCH + 1] = a1 * inv;
        sOut[d*HC + h*CCH + 2] = a2 * inv;
    }
    __syncthreads();
    // head-mean + bias + ELU + graph mean pool
    if (tid < NPG) {
#pragma unroll
        for (int c = 0; c < CCH; c++) {
            float v = 0.f;
#pragma unroll
            for (int h = 0; h < HEADS; h++) v += sOut[tid*HC + h*CCH + c];
            v = v * (1.f/HEADS) + sBias[c];
            v = v > 0.f ? v : expm1f(v);
            atomicAdd(&sPool[c], v);
        }
    }
    __syncthreads();
    if (tid < CCH) g_pooled[band][g][tid] = sPool[tid] * (1.f/NPG);
}

// ---------------- kernel 4: LayerNorm on de ----------------
__global__ __launch_bounds__(256) void ln_kernel(const float* __restrict__ de,
                                                 const float* __restrict__ lg,
                                                 const float* __restrict__ lb)
{
    int b = blockIdx.x;
    const float* row = de + (size_t)b * DEDIM;
    float s = 0.f, q = 0.f;
    for (int i = threadIdx.x; i < DEDIM; i += 256) {
        float v = row[i];
        s += v; q += v*v;
    }
#pragma unroll
    for (int o = 16; o; o >>= 1) {
        s += __shfl_xor_sync(0xffffffffu, s, o);
        q += __shfl_xor_sync(0xffffffffu, q, o);
    }
    __shared__ float rs[8], rq[8];
    __shared__ float sMu, sInv;
    int w = threadIdx.x >> 5, lane = threadIdx.x & 31;
    if (lane == 0) { rs[w] = s; rq[w] = q; }
    __syncthreads();
    if (threadIdx.x == 0) {
        float S = 0.f, Q = 0.f;
#pragma unroll
        for (int ww = 0; ww < 8; ww++) { S += rs[ww]; Q += rq[ww]; }
        float mu = S * (1.f/DEDIM);
        float var = Q * (1.f/DEDIM) - mu*mu;
        sMu = mu; sInv = rsqrtf(var + 1e-5f);
    }
    __syncthreads();
    float mu = sMu, inv = sInv;
    for (int i = threadIdx.x; i < DEDIM; i += 256)
        g_den[b][i] = (row[i] - mu) * inv * lg[i] + lb[i];
}

// ---------------- kernel 5: QKV GEMM [512,930]x[930,64] x3 ----------------
#define BM 16
#define BK 32
__global__ __launch_bounds__(256) void qkv_gemm_kernel(
    const float* __restrict__ qW, const float* __restrict__ qb,
    const float* __restrict__ kW, const float* __restrict__ kb,
    const float* __restrict__ vW, const float* __restrict__ vb)
{
    int mt = blockIdx.x;              // 32 row-tiles of 16
    int which = blockIdx.y;           // 0=Q 1=K 2=V
    const float* Wm = (which == 0) ? qW : (which == 1) ? kW : vW;
    const float* bm = (which == 0) ? qb : (which == 1) ? kb : vb;
    float* Om = (which == 0) ? &g_Q[0][0] : (which == 1) ? &g_K[0][0] : &g_V[0][0];

    __shared__ float As[BM][BK+1];
    __shared__ float Bs[BK][64];
    int tid = threadIdx.x;
    int row = tid >> 4;               // 0..15
    int colg = (tid & 15) * 4;        // 0..60
    float acc0 = 0.f, acc1 = 0.f, acc2 = 0.f, acc3 = 0.f;
    int row0 = mt * BM;
    for (int k0 = 0; k0 < DEDIM; k0 += BK) {
#pragma unroll
        for (int t = 0; t < 2; t++) {
            int idx = tid + t*256;            // 512 A elems
            int r = idx >> 5, c = idx & 31;
            int kc = k0 + c;
            As[r][c] = (kc < DEDIM) ? g_den[row0 + r][kc] : 0.f;
        }
#pragma unroll
        for (int t = 0; t < 8; t++) {
            int idx = tid + t*256;            // 2048 B elems
            int r = idx >> 6, c = idx & 63;
            int kc = k0 + r;
            Bs[r][c] = (kc < DEDIM) ? Wm[kc*64 + c] : 0.f;
        }
        __syncthreads();
#pragma unroll
        for (int kk = 0; kk < BK; kk++) {
            float a = As[row][kk];
            acc0 += a * Bs[kk][colg+0];
            acc1 += a * Bs[kk][colg+1];
            acc2 += a * Bs[kk][colg+2];
            acc3 += a * Bs[kk][colg+3];
        }
        __syncthreads();
    }
    float* orow = Om + (size_t)(row0 + row) * 64 + colg;
    orow[0] = acc0 + bm[colg+0];
    orow[1] = acc1 + bm[colg+1];
    orow[2] = acc2 + bm[colg+2];
    orow[3] = acc3 + bm[colg+3];
}

// ---------------- kernel 6: attention + head fusion + final FC ----------------
__global__ __launch_bounds__(256) void attn_kernel(
    const float* __restrict__ fgW, const float* __restrict__ fgB,
    const float* __restrict__ faW, const float* __restrict__ faB,
    float* __restrict__ out)
{
    int i = blockIdx.x;
    __shared__ float sQ[64], sSc[BGRAPH], sXout[64], sXde[64], sAcc[256];
    __shared__ float sRed[8];
    __shared__ float sMax, sSum;
    int tid = threadIdx.x, lane = tid & 31, w = tid >> 5;

    if (tid < 64) {
        sQ[tid] = g_Q[i][tid];
        // x_out = elu(x_concat @ fg_W + fg_b), x_concat[k] = pooled[k/3][i][k%3]
        float a = fgB[tid];
#pragma unroll
        for (int k = 0; k < NBANDS*CCH; k++)
            a += g_pooled[k/CCH][i][k%CCH] * fgW[k*64 + tid];
        sXout[tid] = a > 0.f ? a : expm1f(a);
    }
    __syncthreads();

    // scores: one warp per j (strided over 512 rows)
    for (int j = w; j < BGRAPH; j += 8) {
        const float* Kj = g_K[j];
        float p = sQ[lane]*Kj[lane] + sQ[lane+32]*Kj[lane+32];
#pragma unroll
        for (int o = 16; o; o >>= 1) p += __shfl_down_sync(0xffffffffu, p, o);
        if (lane == 0) sSc[j] = p * 0.125f;   // 1/sqrt(64)
    }
    __syncthreads();

    // softmax over 512
    float m = fmaxf(sSc[tid], sSc[tid+256]);
#pragma unroll
    for (int o = 16; o; o >>= 1) m = fmaxf(m, __shfl_xor_sync(0xffffffffu, m, o));
    if (lane == 0) sRed[w] = m;
    __syncthreads();
    if (tid == 0) {
        float mm = sRed[0];
#pragma unroll
        for (int k = 1; k < 8; k++) mm = fmaxf(mm, sRed[k]);
        sMax = mm;
    }
    __syncthreads();
    float e0 = __expf(sSc[tid]       - sMax);
    float e1 = __expf(sSc[tid + 256] - sMax);
    sSc[tid] = e0; sSc[tid+256] = e1;
    float ps = e0 + e1;
#pragma unroll
    for (int o = 16; o; o >>= 1) ps += __shfl_xor_sync(0xffffffffu, ps, o);
    if (lane == 0) sRed[w] = ps;
    __syncthreads();
    if (tid == 0) {
        float ss = 0.f;
#pragma unroll
        for (int k = 0; k < 8; k++) ss += sRed[k];
        sSum = ss;
    }
    __syncthreads();

    // x_de = (weights @ V) / sum
    int c = tid & 63, part = tid >> 6;
    float acc = 0.f;
    for (int j = part; j < BGRAPH; j += 4)
        acc += sSc[j] * g_V[j][c];
    sAcc[tid] = acc;
    __syncthreads();
    if (tid < 64)
        sXde[tid] = (sAcc[tid] + sAcc[tid+64] + sAcc[tid+128] + sAcc[tid+192]) / sSum;
    __syncthreads();

    // final: out = elu([x_out, x_de] @ fa_W + fa_b)
    if (w < CCH) {
        float p = 0.f;
#pragma unroll
        for (int r = 0; r < 4; r++) {
            int k = lane + r*32;
            float v = (k < 64) ? sXout[k] : sXde[k-64];
            p += v * faW[k*CCH + w];
        }
#pragma unroll
        for (int o = 16; o; o >>= 1) p += __shfl_down_sync(0xffffffffu, p, o);
        if (lane == 0) {
            float o2 = p + faB[w];
            out[(size_t)i*CCH + w] = o2 > 0.f ? o2 : expm1f(o2);
        }
    }
}

// ---------------- launch ----------------
extern "C" void kernel_launch(void* const* d_in, const int* in_sizes, int n_in,
                              void* d_out, int out_size)
{
    const float* x      = (const float*)d_in[0];   // [5, 31744, 5]
    const int*   ei     = (const int*)  d_in[1];   // [5, 2, 507904]
    // d_in[2] = batch (unused; graphs are 62 contiguous nodes)
    const float* de     = (const float*)d_in[3];   // [512, 62, 5, 3] -> [512,930]
    const float* bn_g   = (const float*)d_in[4];
    const float* bn_b   = (const float*)d_in[5];
    const float* W      = (const float*)d_in[6];
    const float* asrc   = (const float*)d_in[7];
    const float* adst   = (const float*)d_in[8];
    const float* gbias  = (const float*)d_in[9];
    const float* fgW    = (const float*)d_in[10];
    const float* fgB    = (const float*)d_in[11];
    const float* lng    = (const float*)d_in[12];
    const float* lnb    = (const float*)d_in[13];
    const float* qW     = (const float*)d_in[14];
    const float* qb     = (const float*)d_in[15];
    const float* kW     = (const float*)d_in[16];
    const float* kb     = (const float*)d_in[17];
    const float* vW     = (const float*)d_in[18];
    const float* vb     = (const float*)d_in[19];
    const float* faW    = (const float*)d_in[20];
    const float* faB    = (const float*)d_in[21];
    float* out = (float*)d_out;

    zero_stats_kernel<<<1, 64>>>();
    bn_partial_kernel<<<dim3(64, NBANDS), 256>>>(x);
    bn_finalize_kernel<<<1, 32>>>(bn_g, bn_b);
    gat_kernel<<<dim3(BGRAPH, NBANDS), 512>>>(x, ei, W, asrc, adst, gbias);
    ln_kernel<<<BGRAPH, 256>>>(de, lng, lnb);
    qkv_gemm_kernel<<<dim3(32, 3), 256>>>(qW, qb, kW, kb, vW, vb);
    attn_kernel<<<BGRAPH, 256>>>(fgW, fgB, faW, faB, out);
}

// round 9
// speedup vs baseline: 1.4528x; 1.4528x over previous
#include <cuda_runtime.h>
#include <cuda_bf16.h>
#include <math.h>

// ---------------- problem constants ----------------
#define NBANDS 5
#define BGRAPH 512
#define NPG    62
#define NTOT   (BGRAPH*NPG)     // 31744
#define FIN    5
#define HEADS  8
#define CCH    3
#define HC     (HEADS*CCH)      // 24
#define EG     992
#define ETOT   (BGRAPH*EG)      // 507904
#define DEDIM  930

// ---------------- device scratch (no allocs allowed) ----------------
__device__ float g_bnsum[NBANDS][FIN];
__device__ float g_bnsq [NBANDS][FIN];
__device__ float g_scale[NBANDS][FIN];
__device__ float g_shift[NBANDS][FIN];
__device__ float g_pooled[NBANDS][BGRAPH][CCH];
__device__ float g_den[BGRAPH][DEDIM];
__device__ float g_Q[BGRAPH][64];
__device__ float g_K[BGRAPH][64];
__device__ float g_V[BGRAPH][64];

// ---------------- kernel 0: zero BN accumulators ----------------
__global__ void zero_stats_kernel() {
    int t = threadIdx.x;
    if (t < NBANDS*FIN) {
        ((float*)g_bnsum)[t] = 0.f;
        ((float*)g_bnsq )[t] = 0.f;
    }
}

// ---------------- kernel 1: BN partial sums ----------------
__global__ __launch_bounds__(256) void bn_partial_kernel(const float* __restrict__ x) {
    int band = blockIdx.y;
    const float* xb = x + (size_t)band * NTOT * FIN;
    float s[FIN], q[FIN];
#pragma unroll
    for (int f = 0; f < FIN; f++) { s[f] = 0.f; q[f] = 0.f; }
    for (int n = blockIdx.x * blockDim.x + threadIdx.x; n < NTOT; n += gridDim.x * blockDim.x) {
#pragma unroll
        for (int f = 0; f < FIN; f++) {
            float v = xb[n*FIN + f];
            s[f] += v; q[f] += v*v;
        }
    }
#pragma unroll
    for (int f = 0; f < FIN; f++) {
#pragma unroll
        for (int o = 16; o; o >>= 1) {
            s[f] += __shfl_xor_sync(0xffffffffu, s[f], o);
            q[f] += __shfl_xor_sync(0xffffffffu, q[f], o);
        }
    }
    __shared__ float rs[8][FIN], rq[8][FIN];
    int w = threadIdx.x >> 5, lane = threadIdx.x & 31;
    if (lane == 0) {
#pragma unroll
        for (int f = 0; f < FIN; f++) { rs[w][f] = s[f]; rq[w][f] = q[f]; }
    }
    __syncthreads();
    if (threadIdx.x < FIN) {
        int f = threadIdx.x;
        float S = 0.f, Q = 0.f;
#pragma unroll
        for (int ww = 0; ww < 8; ww++) { S += rs[ww][f]; Q += rq[ww][f]; }
        atomicAdd(&g_bnsum[band][f], S);
        atomicAdd(&g_bnsq [band][f], Q);
    }
}

// ---------------- kernel 2: finalize BN scale/shift ----------------
__global__ void bn_finalize_kernel(const float* __restrict__ gamma,
                                   const float* __restrict__ beta) {
    int t = threadIdx.x;
    if (t < NBANDS*FIN) {
        int band = t / FIN, f = t % FIN;
        float mu  = g_bnsum[band][f] * (1.f / NTOT);
        float var = g_bnsq [band][f] * (1.f / NTOT) - mu*mu;
        float sc  = gamma[t] * rsqrtf(var + 1e-5f);
        g_scale[band][f] = sc;
        g_shift[band][f] = beta[t] - mu*sc;
    }
}

// ---------------- kernel 3: per-(band,graph) GAT + pool ----------------
// 512 threads. Node state float4 (xt0,xt1,xt2,al_src).
// Aggregation mapping d=tid>>3, h=tid&7: csr broadcast + conflict-free LDS.
__global__ __launch_bounds__(512) void gat_kernel(
    const float* __restrict__ x, const int* __restrict__ ei,
    const float* __restrict__ W, const float* __restrict__ asrc,
    const float* __restrict__ adst, const float* __restrict__ gbias)
{
    int g = blockIdx.x, band = blockIdx.y;
    __shared__ float  sW[FIN*HC];
    __shared__ float  sAS[HC], sAD[HC];
    __shared__ float  sSc[FIN], sSh[FIN], sBias[CCH];
    __shared__ float  sXN[NPG*FIN];
    __shared__ float4 sXT4[NPG*HEADS];      // [n][h] -> (xt0,xt1,xt2,al_src)
    __shared__ float  sALD[NPG*HEADS];      // [n][h]
    __shared__ int    sCnt[NPG];
    __shared__ int    sOff[NPG+1];
    __shared__ int    sPos[NPG];
    __shared__ int    sCsr[NPG + EG];
    __shared__ __align__(16) float sOutT[NPG*HC];  // [d][c][h] transposed, 16B-aligned
    __shared__ float  sPool[CCH];

    int tid = threadIdx.x;
    // ---- stage params (disjoint ranges) + load my edges into registers ----
    const int* e0 = ei + ((size_t)band*2 + 0)*ETOT + (size_t)g*EG;
    const int* e1 = ei + ((size_t)band*2 + 1)*ETOT + (size_t)g*EG;
    int gbase = g * NPG;
    int myS0 = e0[tid] - gbase;             // tid < 512 <= EG always valid
    int myD0 = e1[tid] - gbase;
    int myS1 = 0, myD1 = -1;
    if (tid + 512 < EG) {
        myS1 = e0[tid + 512] - gbase;
        myD1 = e1[tid + 512] - gbase;
    }

    if (tid < FIN*HC)                   sW[tid]       = W[band*FIN*HC + tid];
    if (tid >= 128 && tid < 128+HC)     sAS[tid-128]  = asrc[band*HC + (tid-128)];
    if (tid >= 160 && tid < 160+HC)     sAD[tid-160]  = adst[band*HC + (tid-160)];
    if (tid >= 192 && tid < 192+FIN)    sSc[tid-192]  = g_scale[band][tid-192];
    if (tid >= 200 && tid < 200+FIN)    sSh[tid-200]  = g_shift[band][tid-200];
    if (tid >= 208 && tid < 208+CCH)    sBias[tid-208]= gbias[band*CCH + (tid-208)];
    if (tid >= 256 && tid < 256+NPG)    sCnt[tid-256] = 1;   // self-loop seed
    if (tid < CCH) sPool[tid] = 0.f;

    __syncthreads();
    // node features (BN applied): 310 elems
    const float* xg = x + ((size_t)band * NTOT + (size_t)g * NPG) * FIN;
    if (tid < NPG*FIN) {
        int f = tid % FIN;
        sXN[tid] = xg[tid] * sSc[f] + sSh[f];
    }
    // in-degree counting
    atomicAdd(&sCnt[myD0], 1);
    if (myD1 >= 0) atomicAdd(&sCnt[myD1], 1);
    __syncthreads();

    // fused projection + logits: item (n,h) (496 items)
    if (tid < NPG*HEADS) {
        int n = tid >> 3, h = tid & 7;
        float x0 = 0.f, x1 = 0.f, x2 = 0.f;
#pragma unroll
        for (int f = 0; f < FIN; f++) {
            float xv = sXN[n*FIN + f];
            x0 += xv * sW[f*HC + h*CCH + 0];
            x1 += xv * sW[f*HC + h*CCH + 1];
            x2 += xv * sW[f*HC + h*CCH + 2];
        }
        float as = x0*sAS[h*CCH+0] + x1*sAS[h*CCH+1] + x2*sAS[h*CCH+2];
        float ad = x0*sAD[h*CCH+0] + x1*sAD[h*CCH+1] + x2*sAD[h*CCH+2];
        sXT4[tid] = make_float4(x0, x1, x2, as);
        sALD[tid] = ad;
    }
    // prefix scan of counts in warp 0 (lane i handles i and i+32)
    if (tid < 32) {
        int lane = tid;
        int c0 = sCnt[lane];
        int c1 = (lane + 32 < NPG) ? sCnt[lane + 32] : 0;
        int cnt0 = c0, cnt1 = c1;
#pragma unroll
        for (int o = 1; o < 32; o <<= 1) {
            int t = __shfl_up_sync(0xffffffffu, c0, o);
            if (lane >= o) c0 += t;
        }
        int tot0 = __shfl_sync(0xffffffffu, c0, 31);
#pragma unroll
        for (int o = 1; o < 32; o <<= 1) {
            int t = __shfl_up_sync(0xffffffffu, c1, o);
            if (lane >= o) c1 += t;
        }
        c1 += tot0;
        sOff[lane] = c0 - cnt0;                        // exclusive
        if (lane + 32 < NPG) sOff[lane + 32] = c1 - cnt1;
        if (lane == 31) sOff[NPG] = c1;                // total = EG + NPG
    }
    __syncthreads();
    if (tid < NPG) { sCsr[sOff[tid]] = tid; sPos[tid] = sOff[tid] + 1; }
    __syncthreads();
    {
        int p = atomicAdd(&sPos[myD0], 1);
        sCsr[p] = myS0;
        if (myD1 >= 0) {
            int p1 = atomicAdd(&sPos[myD1], 1);
            sCsr[p1] = myS1;
        }
    }
    __syncthreads();

    // dst-major softmax aggregation: thread item (d,h), h fastest.
    // 8 lanes of a head-group share d -> sCsr broadcast; sXT4 row = 128B CF.
    if (tid < NPG*HEADS) {
        int d = tid >> 3, h = tid & 7;
        float ald = sALD[tid];
        float den = 0.f, a0 = 0.f, a1 = 0.f, a2 = 0.f;
        int k0 = sOff[d], k1 = sOff[d+1];
        for (int k = k0; k < k1; k++) {
            int s = sCsr[k];                      // broadcast across 8 lanes
            float4 v = sXT4[s*HEADS + h];         // contiguous 128B per group
            float al = v.w + ald;
            float ev = al > 0.f ? al : 0.2f * al; // leaky_relu(0.2)
            float ex = __expf(ev);                // logits O(1): no max shift
            den += ex;
            a0 += ex * v.x; a1 += ex * v.y; a2 += ex * v.z;
        }
        float inv = 1.f / den;
        // transposed store [d][c][h]: conflict-free
        sOutT[d*HC + 0*HEADS + h] = a0 * inv;
        sOutT[d*HC + 1*HEADS + h] = a1 * inv;
        sOutT[d*HC + 2*HEADS + h] = a2 * inv;
    }
    __syncthreads();
    // head-mean + bias + ELU + graph mean pool (vectorized reads)
    if (tid < NPG) {
        const float4* v4 = (const float4*)sOutT;   // 6 float4 per dst (aligned)
#pragma unroll
        for (int c = 0; c < CCH; c++) {
            float4 f0 = v4[tid*6 + c*2 + 0];
            float4 f1 = v4[tid*6 + c*2 + 1];
            float v = (f0.x+f0.y+f0.z+f0.w) + (f1.x+f1.y+f1.z+f1.w);
            v = v * (1.f/HEADS) + sBias[c];
            v = v > 0.f ? v : expm1f(v);
            atomicAdd(&sPool[c], v);
        }
    }
    __syncthreads();
    if (tid < CCH) g_pooled[band][g][tid] = sPool[tid] * (1.f/NPG);
}

// ---------------- kernel 4: LayerNorm on de ----------------
__global__ __launch_bounds__(256) void ln_kernel(const float* __restrict__ de,
                                                 const float* __restrict__ lg,
                                                 const float* __restrict__ lb)
{
    int b = blockIdx.x;
    const float* row = de + (size_t)b * DEDIM;
    float s = 0.f, q = 0.f;
    for (int i = threadIdx.x; i < DEDIM; i += 256) {
        float v = row[i];
        s += v; q += v*v;
    }
#pragma unroll
    for (int o = 16; o; o >>= 1) {
        s += __shfl_xor_sync(0xffffffffu, s, o);
        q += __shfl_xor_sync(0xffffffffu, q, o);
    }
    __shared__ float rs[8], rq[8];
    __shared__ float sMu, sInv;
    int w = threadIdx.x >> 5, lane = threadIdx.x & 31;
    if (lane == 0) { rs[w] = s; rq[w] = q; }
    __syncthreads();
    if (threadIdx.x == 0) {
        float S = 0.f, Q = 0.f;
#pragma unroll
        for (int ww = 0; ww < 8; ww++) { S += rs[ww]; Q += rq[ww]; }
        float mu = S * (1.f/DEDIM);
        float var = Q * (1.f/DEDIM) - mu*mu;
        sMu = mu; sInv = rsqrtf(var + 1e-5f);
    }
    __syncthreads();
    float mu = sMu, inv = sInv;
    for (int i = threadIdx.x; i < DEDIM; i += 256)
        g_den[b][i] = (row[i] - mu) * inv * lg[i] + lb[i];
}

// ---------------- kernel 5: QKV GEMM [512,930]x[930,64] x3 ----------------
#define BM 16
#define BK 32
__global__ __launch_bounds__(256) void qkv_gemm_kernel(
    const float* __restrict__ qW, const float* __restrict__ qb,
    const float* __restrict__ kW, const float* __restrict__ kb,
    const float* __restrict__ vW, const float* __restrict__ vb)
{
    int mt = blockIdx.x;              // 32 row-tiles of 16
    int which = blockIdx.y;           // 0=Q 1=K 2=V
    const float* Wm = (which == 0) ? qW : (which == 1) ? kW : vW;
    const float* bm = (which == 0) ? qb : (which == 1) ? kb : vb;
    float* Om = (which == 0) ? &g_Q[0][0] : (which == 1) ? &g_K[0][0] : &g_V[0][0];

    __shared__ float As[BM][BK+1];
    __shared__ float Bs[BK][64];
    int tid = threadIdx.x;
    int row = tid >> 4;               // 0..15
    int colg = (tid & 15) * 4;        // 0..60
    float acc0 = 0.f, acc1 = 0.f, acc2 = 0.f, acc3 = 0.f;
    int row0 = mt * BM;
    for (int k0 = 0; k0 < DEDIM; k0 += BK) {
#pragma unroll
        for (int t = 0; t < 2; t++) {
            int idx = tid + t*256;            // 512 A elems
            int r = idx >> 5, c = idx & 31;
            int kc = k0 + c;
            As[r][c] = (kc < DEDIM) ? g_den[row0 + r][kc] : 0.f;
        }
#pragma unroll
        for (int t = 0; t < 8; t++) {
            int idx = tid + t*256;            // 2048 B elems
            int r = idx >> 6, c = idx & 63;
            int kc = k0 + r;
            Bs[r][c] = (kc < DEDIM) ? Wm[kc*64 + c] : 0.f;
        }
        __syncthreads();
#pragma unroll
        for (int kk = 0; kk < BK; kk++) {
            float a = As[row][kk];
            acc0 += a * Bs[kk][colg+0];
            acc1 += a * Bs[kk][colg+1];
            acc2 += a * Bs[kk][colg+2];
            acc3 += a * Bs[kk][colg+3];
        }
        __syncthreads();
    }
    float* orow = Om + (size_t)(row0 + row) * 64 + colg;
    orow[0] = acc0 + bm[colg+0];
    orow[1] = acc1 + bm[colg+1];
    orow[2] = acc2 + bm[colg+2];
    orow[3] = acc3 + bm[colg+3];
}

// ---------------- kernel 6: attention + head fusion + final FC ----------------
__global__ __launch_bounds__(256) void attn_kernel(
    const float* __restrict__ fgW, const float* __restrict__ fgB,
    const float* __restrict__ faW, const float* __restrict__ faB,
    float* __restrict__ out)
{
    int i = blockIdx.x;
    __shared__ float sQ[64], sSc[BGRAPH], sXout[64], sXde[64], sAcc[256];
    __shared__ float sRed[8];
    __shared__ float sMax, sSum;
    int tid = threadIdx.x, lane = tid & 31, w = tid >> 5;

    if (tid < 64) {
        sQ[tid] = g_Q[i][tid];
        // x_out = elu(x_concat @ fg_W + fg_b), x_concat[k] = pooled[k/3][i][k%3]
        float a = fgB[tid];
#pragma unroll
        for (int k = 0; k < NBANDS*CCH; k++)
            a += g_pooled[k/CCH][i][k%CCH] * fgW[k*64 + tid];
        sXout[tid] = a > 0.f ? a : expm1f(a);
    }
    __syncthreads();

    // scores: one warp per j (strided over 512 rows)
    for (int j = w; j < BGRAPH; j += 8) {
        const float* Kj = g_K[j];
        float p = sQ[lane]*Kj[lane] + sQ[lane+32]*Kj[lane+32];
#pragma unroll
        for (int o = 16; o; o >>= 1) p += __shfl_down_sync(0xffffffffu, p, o);
        if (lane == 0) sSc[j] = p * 0.125f;   // 1/sqrt(64)
    }
    __syncthreads();

    // softmax over 512
    float m = fmaxf(sSc[tid], sSc[tid+256]);
#pragma unroll
    for (int o = 16; o; o >>= 1) m = fmaxf(m, __shfl_xor_sync(0xffffffffu, m, o));
    if (lane == 0) sRed[w] = m;
    __syncthreads();
    if (tid == 0) {
        float mm = sRed[0];
#pragma unroll
        for (int k = 1; k < 8; k++) mm = fmaxf(mm, sRed[k]);
        sMax = mm;
    }
    __syncthreads();
    float e0 = __expf(sSc[tid]       - sMax);
    float e1 = __expf(sSc[tid + 256] - sMax);
    sSc[tid] = e0; sSc[tid+256] = e1;
    float ps = e0 + e1;
#pragma unroll
    for (int o = 16; o; o >>= 1) ps += __shfl_xor_sync(0xffffffffu, ps, o);
    if (lane == 0) sRed[w] = ps;
    __syncthreads();
    if (tid == 0) {
        float ss = 0.f;
#pragma unroll
        for (int k = 0; k < 8; k++) ss += sRed[k];
        sSum = ss;
    }
    __syncthreads();

    // x_de = (weights @ V) / sum
    int c = tid & 63, part = tid >> 6;
    float acc = 0.f;
    for (int j = part; j < BGRAPH; j += 4)
        acc += sSc[j] * g_V[j][c];
    sAcc[tid] = acc;
    __syncthreads();
    if (tid < 64)
        sXde[tid] = (sAcc[tid] + sAcc[tid+64] + sAcc[tid+128] + sAcc[tid+192]) / sSum;
    __syncthreads();

    // final: out = elu([x_out, x_de] @ fa_W + fa_b)
    if (w < CCH) {
        float p = 0.f;
#pragma unroll
        for (int r = 0; r < 4; r++) {
            int k = lane + r*32;
            float v = (k < 64) ? sXout[k] : sXde[k-64];
            p += v * faW[k*CCH + w];
        }
#pragma unroll
        for (int o = 16; o; o >>= 1) p += __shfl_down_sync(0xffffffffu, p, o);
        if (lane == 0) {
            float o2 = p + faB[w];
            out[(size_t)i*CCH + w] = o2 > 0.f ? o2 : expm1f(o2);
        }
    }
}

// ---------------- launch ----------------
extern "C" void kernel_launch(void* const* d_in, const int* in_sizes, int n_in,
                              void* d_out, int out_size)
{
    const float* x      = (const float*)d_in[0];   // [5, 31744, 5]
    const int*   ei     = (const int*)  d_in[1];   // [5, 2, 507904]
    // d_in[2] = batch (unused; graphs are 62 contiguous nodes)
    const float* de     = (const float*)d_in[3];   // [512, 62, 5, 3] -> [512,930]
    const float* bn_g   = (const float*)d_in[4];
    const float* bn_b   = (const float*)d_in[5];
    const float* W      = (const float*)d_in[6];
    const float* asrc   = (const float*)d_in[7];
    const float* adst   = (const float*)d_in[8];
    const float* gbias  = (const float*)d_in[9];
    const float* fgW    = (const float*)d_in[10];
    const float* fgB    = (const float*)d_in[11];
    const float* lng    = (const float*)d_in[12];
    const float* lnb    = (const float*)d_in[13];
    const float* qW     = (const float*)d_in[14];
    const float* qb     = (const float*)d_in[15];
    const float* kW     = (const float*)d_in[16];
    const float* kb     = (const float*)d_in[17];
    const float* vW     = (const float*)d_in[18];
    const float* vb     = (const float*)d_in[19];
    const float* faW    = (const float*)d_in[20];
    const float* faB    = (const float*)d_in[21];
    float* out = (float*)d_out;

    zero_stats_kernel<<<1, 64>>>();
    bn_partial_kernel<<<dim3(64, NBANDS), 256>>>(x);
    bn_finalize_kernel<<<1, 32>>>(bn_g, bn_b);
    gat_kernel<<<dim3(BGRAPH, NBANDS), 512>>>(x, ei, W, asrc, adst, gbias);
    ln_kernel<<<BGRAPH, 256>>>(de, lng, lnb);
    qkv_gemm_kernel<<<dim3(32, 3), 256>>>(qW, qb, kW, kb, vW, vb);
    attn_kernel<<<BGRAPH, 256>>>(fgW, fgB, faW, faB, out);
}

// round 10
// speedup vs baseline: 1.5677x; 1.0791x over previous
#include <cuda_runtime.h>
#include <cuda_bf16.h>
#include <math.h>

// ---------------- problem constants ----------------
#define NBANDS 5
#define BGRAPH 512
#define NPG    62
#define NTOT   (BGRAPH*NPG)     // 31744
#define FIN    5
#define HEADS  8
#define CCH    3
#define HC     (HEADS*CCH)      // 24
#define EG     992
#define ETOT   (BGRAPH*EG)      // 507904
#define DEDIM  930
#define NBNBLK 64

// ---------------- device scratch (no allocs allowed) ----------------
__device__ float g_bnpart_s[NBANDS][NBNBLK][FIN];
__device__ float g_bnpart_q[NBANDS][NBNBLK][FIN];
__device__ float g_scale[NBANDS][FIN];
__device__ float g_shift[NBANDS][FIN];
__device__ float g_pooled[NBANDS][BGRAPH][CCH];
__device__ float g_mu[BGRAPH];
__device__ float g_inv[BGRAPH];
__device__ float g_Q[BGRAPH][64];
__device__ float g_K[BGRAPH][64];
__device__ float g_V[BGRAPH][64];

// FMA-pipe exp: 2^n * poly6(f). rel err ~2e-5, no MUFU.
__device__ __forceinline__ float fexp(float x) {
    float y = x * 1.4426950408889634f;
    float n = floorf(y);
    float f = y - n;
    float p = 1.5403530393381609e-4f;
    p = fmaf(p, f, 1.3333558146428443e-3f);
    p = fmaf(p, f, 9.6181291076284772e-3f);
    p = fmaf(p, f, 5.5504108664821580e-2f);
    p = fmaf(p, f, 2.4022650695910071e-1f);
    p = fmaf(p, f, 6.9314718055994531e-1f);
    p = fmaf(p, f, 1.0f);
    float s = __int_as_float(((int)n + 127) << 23);
    return p * s;
}

// ---------------- kernel 1: BN partial sums (slot writes, no atomics) ----------------
__global__ __launch_bounds__(256) void bn_partial_kernel(const float* __restrict__ x) {
    int band = blockIdx.y;
    const float* xb = x + (size_t)band * NTOT * FIN;
    float s[FIN], q[FIN];
#pragma unroll
    for (int f = 0; f < FIN; f++) { s[f] = 0.f; q[f] = 0.f; }
    for (int n = blockIdx.x * blockDim.x + threadIdx.x; n < NTOT; n += gridDim.x * blockDim.x) {
#pragma unroll
        for (int f = 0; f < FIN; f++) {
            float v = xb[n*FIN + f];
            s[f] += v; q[f] += v*v;
        }
    }
#pragma unroll
    for (int f = 0; f < FIN; f++) {
#pragma unroll
        for (int o = 16; o; o >>= 1) {
            s[f] += __shfl_xor_sync(0xffffffffu, s[f], o);
            q[f] += __shfl_xor_sync(0xffffffffu, q[f], o);
        }
    }
    __shared__ float rs[8][FIN], rq[8][FIN];
    int w = threadIdx.x >> 5, lane = threadIdx.x & 31;
    if (lane == 0) {
#pragma unroll
        for (int f = 0; f < FIN; f++) { rs[w][f] = s[f]; rq[w][f] = q[f]; }
    }
    __syncthreads();
    if (threadIdx.x < FIN) {
        int f = threadIdx.x;
        float S = 0.f, Q = 0.f;
#pragma unroll
        for (int ww = 0; ww < 8; ww++) { S += rs[ww][f]; Q += rq[ww][f]; }
        g_bnpart_s[band][blockIdx.x][f] = S;
        g_bnpart_q[band][blockIdx.x][f] = Q;
    }
}

// ---------------- kernel 2: finalize BN scale/shift ----------------
__global__ void bn_finalize_kernel(const float* __restrict__ gamma,
                                   const float* __restrict__ beta) {
    int t = threadIdx.x;
    if (t < NBANDS*FIN) {
        int band = t / FIN, f = t % FIN;
        float S = 0.f, Q = 0.f;
#pragma unroll 8
        for (int b = 0; b < NBNBLK; b++) {
            S += g_bnpart_s[band][b][f];
            Q += g_bnpart_q[band][b][f];
        }
        float mu  = S * (1.f / NTOT);
        float var = Q * (1.f / NTOT) - mu*mu;
        float sc  = gamma[t] * rsqrtf(var + 1e-5f);
        g_scale[band][f] = sc;
        g_shift[band][f] = beta[t] - mu*sc;
    }
}

// ---------------- kernel 3: per-(band,graph) GAT + pool ----------------
__global__ __launch_bounds__(512) void gat_kernel(
    const float* __restrict__ x, const int* __restrict__ ei,
    const float* __restrict__ W, const float* __restrict__ asrc,
    const float* __restrict__ adst, const float* __restrict__ gbias)
{
    int g = blockIdx.x, band = blockIdx.y;
    __shared__ float  sW[FIN*HC];
    __shared__ float  sAS[HC], sAD[HC];
    __shared__ float  sSc[FIN], sSh[FIN], sBias[CCH];
    __shared__ float  sXN[NPG*FIN];
    __shared__ float4 sXT4[NPG*HEADS];      // [n][h] -> (xt0,xt1,xt2,al_src)
    __shared__ float  sALD[NPG*HEADS];      // [n][h]
    __shared__ int    sCnt[NPG];
    __shared__ int    sOff[NPG+1];
    __shared__ int    sPos[NPG];
    __shared__ int    sCsr[NPG + EG];
    __shared__ __align__(16) float sOutT[NPG*HC];  // [d][c][h]
    __shared__ float  sPool[CCH];

    int tid = threadIdx.x;
    const int* e0 = ei + ((size_t)band*2 + 0)*ETOT + (size_t)g*EG;
    const int* e1 = ei + ((size_t)band*2 + 1)*ETOT + (size_t)g*EG;
    int gbase = g * NPG;
    int myS0 = e0[tid] - gbase;
    int myD0 = e1[tid] - gbase;
    int myS1 = 0, myD1 = -1;
    if (tid + 512 < EG) {
        myS1 = e0[tid + 512] - gbase;
        myD1 = e1[tid + 512] - gbase;
    }

    if (tid < FIN*HC)                   sW[tid]       = W[band*FIN*HC + tid];
    if (tid >= 128 && tid < 128+HC)     sAS[tid-128]  = asrc[band*HC + (tid-128)];
    if (tid >= 160 && tid < 160+HC)     sAD[tid-160]  = adst[band*HC + (tid-160)];
    if (tid >= 192 && tid < 192+FIN)    sSc[tid-192]  = g_scale[band][tid-192];
    if (tid >= 200 && tid < 200+FIN)    sSh[tid-200]  = g_shift[band][tid-200];
    if (tid >= 208 && tid < 208+CCH)    sBias[tid-208]= gbias[band*CCH + (tid-208)];
    if (tid >= 256 && tid < 256+NPG)    sCnt[tid-256] = 1;   // self-loop seed
    if (tid < CCH) sPool[tid] = 0.f;

    __syncthreads();
    const float* xg = x + ((size_t)band * NTOT + (size_t)g * NPG) * FIN;
    if (tid < NPG*FIN) {
        int f = tid % FIN;
        sXN[tid] = xg[tid] * sSc[f] + sSh[f];
    }
    atomicAdd(&sCnt[myD0], 1);
    if (myD1 >= 0) atomicAdd(&sCnt[myD1], 1);
    __syncthreads();

    // fused projection + logits
    if (tid < NPG*HEADS) {
        int n = tid >> 3, h = tid & 7;
        float x0 = 0.f, x1 = 0.f, x2 = 0.f;
#pragma unroll
        for (int f = 0; f < FIN; f++) {
            float xv = sXN[n*FIN + f];
            x0 += xv * sW[f*HC + h*CCH + 0];
            x1 += xv * sW[f*HC + h*CCH + 1];
            x2 += xv * sW[f*HC + h*CCH + 2];
        }
        float as = x0*sAS[h*CCH+0] + x1*sAS[h*CCH+1] + x2*sAS[h*CCH+2];
        float ad = x0*sAD[h*CCH+0] + x1*sAD[h*CCH+1] + x2*sAD[h*CCH+2];
        sXT4[tid] = make_float4(x0, x1, x2, as);
        sALD[tid] = ad;
    }
    // warp-scan CSR offsets
    if (tid < 32) {
        int lane = tid;
        int c0 = sCnt[lane];
        int c1 = (lane + 32 < NPG) ? sCnt[lane + 32] : 0;
        int cnt0 = c0, cnt1 = c1;
#pragma unroll
        for (int o = 1; o < 32; o <<= 1) {
            int t = __shfl_up_sync(0xffffffffu, c0, o);
            if (lane >= o) c0 += t;
        }
        int tot0 = __shfl_sync(0xffffffffu, c0, 31);
#pragma unroll
        for (int o = 1; o < 32; o <<= 1) {
            int t = __shfl_up_sync(0xffffffffu, c1, o);
            if (lane >= o) c1 += t;
        }
        c1 += tot0;
        sOff[lane] = c0 - cnt0;
        if (lane + 32 < NPG) sOff[lane + 32] = c1 - cnt1;
        if (lane == 31) sOff[NPG] = c1;
    }
    __syncthreads();
    if (tid < NPG) { sCsr[sOff[tid]] = tid; sPos[tid] = sOff[tid] + 1; }
    __syncthreads();
    {
        int p = atomicAdd(&sPos[myD0], 1);
        sCsr[p] = myS0;
        if (myD1 >= 0) {
            int p1 = atomicAdd(&sPos[myD1], 1);
            sCsr[p1] = myS1;
        }
    }
    __syncthreads();

    // dst-major softmax aggregation (conflict-free; FMA-pipe exp)
    if (tid < NPG*HEADS) {
        int d = tid >> 3, h = tid & 7;
        float ald = sALD[tid];
        float den = 0.f, a0 = 0.f, a1 = 0.f, a2 = 0.f;
        int k0 = sOff[d], k1 = sOff[d+1];
        for (int k = k0; k < k1; k++) {
            int s = sCsr[k];
            float4 v = sXT4[s*HEADS + h];
            float al = v.w + ald;
            float ev = al > 0.f ? al : 0.2f * al;
            float ex = fexp(ev);
            den += ex;
            a0 += ex * v.x; a1 += ex * v.y; a2 += ex * v.z;
        }
        float inv = 1.f / den;
        sOutT[d*HC + 0*HEADS + h] = a0 * inv;
        sOutT[d*HC + 1*HEADS + h] = a1 * inv;
        sOutT[d*HC + 2*HEADS + h] = a2 * inv;
    }
    __syncthreads();
    if (tid < NPG) {
        const float4* v4 = (const float4*)sOutT;
#pragma unroll
        for (int c = 0; c < CCH; c++) {
            float4 f0 = v4[tid*6 + c*2 + 0];
            float4 f1 = v4[tid*6 + c*2 + 1];
            float v = (f0.x+f0.y+f0.z+f0.w) + (f1.x+f1.y+f1.z+f1.w);
            v = v * (1.f/HEADS) + sBias[c];
            v = v > 0.f ? v : expm1f(v);
            atomicAdd(&sPool[c], v);
        }
    }
    __syncthreads();
    if (tid < CCH) g_pooled[band][g][tid] = sPool[tid] * (1.f/NPG);
}

// ---------------- kernel 4: LN row stats only (mu, inv) ----------------
__global__ __launch_bounds__(256) void ln_stats_kernel(const float* __restrict__ de) {
    int b = blockIdx.x;
    const float* row = de + (size_t)b * DEDIM;
    float s = 0.f, q = 0.f;
    for (int i = threadIdx.x; i < DEDIM; i += 256) {
        float v = row[i];
        s += v; q += v*v;
    }
#pragma unroll
    for (int o = 16; o; o >>= 1) {
        s += __shfl_xor_sync(0xffffffffu, s, o);
        q += __shfl_xor_sync(0xffffffffu, q, o);
    }
    __shared__ float rs[8], rq[8];
    int w = threadIdx.x >> 5, lane = threadIdx.x & 31;
    if (lane == 0) { rs[w] = s; rq[w] = q; }
    __syncthreads();
    if (threadIdx.x == 0) {
        float S = 0.f, Q = 0.f;
#pragma unroll
        for (int ww = 0; ww < 8; ww++) { S += rs[ww]; Q += rq[ww]; }
        float mu = S * (1.f/DEDIM);
        float var = Q * (1.f/DEDIM) - mu*mu;
        g_mu[b]  = mu;
        g_inv[b] = rsqrtf(var + 1e-5f);
    }
}

// ---------------- kernel 5: QKV GEMM with fused LayerNorm on A-load ----------------
#define BM 16
#define BK 32
__global__ __launch_bounds__(256) void qkv_gemm_kernel(
    const float* __restrict__ de,
    const float* __restrict__ lg, const float* __restrict__ lb,
    const float* __restrict__ qW, const float* __restrict__ qb,
    const float* __restrict__ kW, const float* __restrict__ kb,
    const float* __restrict__ vW, const float* __restrict__ vb)
{
    int mt = blockIdx.x;              // 32 row-tiles of 16
    int which = blockIdx.y;           // 0=Q 1=K 2=V
    const float* Wm = (which == 0) ? qW : (which == 1) ? kW : vW;
    const float* bm = (which == 0) ? qb : (which == 1) ? kb : vb;
    float* Om = (which == 0) ? &g_Q[0][0] : (which == 1) ? &g_K[0][0] : &g_V[0][0];

    __shared__ float As[BM][BK+1];
    __shared__ float Bs[BK][64];
    __shared__ float sMu[BM], sInv[BM];
    int tid = threadIdx.x;
    int row = tid >> 4;               // 0..15
    int colg = (tid & 15) * 4;        // 0..60
    int row0 = mt * BM;
    if (tid < BM) { sMu[tid] = g_mu[row0 + tid]; sInv[tid] = g_inv[row0 + tid]; }
    __syncthreads();
    float acc0 = 0.f, acc1 = 0.f, acc2 = 0.f, acc3 = 0.f;
    for (int k0 = 0; k0 < DEDIM; k0 += BK) {
#pragma unroll
        for (int t = 0; t < 2; t++) {
            int idx = tid + t*256;            // 512 A elems
            int r = idx >> 5, c = idx & 31;
            int kc = k0 + c;
            float v = 0.f;
            if (kc < DEDIM) {
                float raw = de[(size_t)(row0 + r)*DEDIM + kc];
                v = (raw - sMu[r]) * sInv[r] * __ldg(&lg[kc]) + __ldg(&lb[kc]);
            }
            As[r][c] = v;
        }
#pragma unroll
        for (int t = 0; t < 8; t++) {
            int idx = tid + t*256;            // 2048 B elems
            int r = idx >> 6, c = idx & 63;
            int kc = k0 + r;
            Bs[r][c] = (kc < DEDIM) ? Wm[kc*64 + c] : 0.f;
        }
        __syncthreads();
#pragma unroll
        for (int kk = 0; kk < BK; kk++) {
            float a = As[row][kk];
            acc0 += a * Bs[kk][colg+0];
            acc1 += a * Bs[kk][colg+1];
            acc2 += a * Bs[kk][colg+2];
            acc3 += a * Bs[kk][colg+3];
        }
        __syncthreads();
    }
    float* orow = Om + (size_t)(row0 + row) * 64 + colg;
    orow[0] = acc0 + bm[colg+0];
    orow[1] = acc1 + bm[colg+1];
    orow[2] = acc2 + bm[colg+2];
    orow[3] = acc3 + bm[colg+3];
}

// ---------------- kernel 6: attention + head fusion + final FC ----------------
__global__ __launch_bounds__(256) void attn_kernel(
    const float* __restrict__ fgW, const float* __restrict__ fgB,
    const float* __restrict__ faW, const float* __restrict__ faB,
    float* __restrict__ out)
{
    int i = blockIdx.x;
    __shared__ float sQ[64], sSc[BGRAPH], sXout[64], sXde[64], sAcc[256];
    __shared__ float sRed[8];
    __shared__ float sMax, sSum;
    int tid = threadIdx.x, lane = tid & 31, w = tid >> 5;

    if (tid < 64) {
        sQ[tid] = g_Q[i][tid];
        float a = fgB[tid];
#pragma unroll
        for (int k = 0; k < NBANDS*CCH; k++)
            a += g_pooled[k/CCH][i][k%CCH] * fgW[k*64 + tid];
        sXout[tid] = a > 0.f ? a : expm1f(a);
    }
    __syncthreads();

    for (int j = w; j < BGRAPH; j += 8) {
        const float* Kj = g_K[j];
        float p = sQ[lane]*Kj[lane] + sQ[lane+32]*Kj[lane+32];
#pragma unroll
        for (int o = 16; o; o >>= 1) p += __shfl_down_sync(0xffffffffu, p, o);
        if (lane == 0) sSc[j] = p * 0.125f;
    }
    __syncthreads();

    float m = fmaxf(sSc[tid], sSc[tid+256]);
#pragma unroll
    for (int o = 16; o; o >>= 1) m = fmaxf(m, __shfl_xor_sync(0xffffffffu, m, o));
    if (lane == 0) sRed[w] = m;
    __syncthreads();
    if (tid == 0) {
        float mm = sRed[0];
#pragma unroll
        for (int k = 1; k < 8; k++) mm = fmaxf(mm, sRed[k]);
        sMax = mm;
    }
    __syncthreads();
    float e0 = __expf(sSc[tid]       - sMax);
    float e1 = __expf(sSc[tid + 256] - sMax);
    sSc[tid] = e0; sSc[tid+256] = e1;
    float ps = e0 + e1;
#pragma unroll
    for (int o = 16; o; o >>= 1) ps += __shfl_xor_sync(0xffffffffu, ps, o);
    if (lane == 0) sRed[w] = ps;
    __syncthreads();
    if (tid == 0) {
        float ss = 0.f;
#pragma unroll
        for (int k = 0; k < 8; k++) ss += sRed[k];
        sSum = ss;
    }
    __syncthreads();

    int c = tid & 63, part = tid >> 6;
    float acc = 0.f;
    for (int j = part; j < BGRAPH; j += 4)
        acc += sSc[j] * g_V[j][c];
    sAcc[tid] = acc;
    __syncthreads();
    if (tid < 64)
        sXde[tid] = (sAcc[tid] + sAcc[tid+64] + sAcc[tid+128] + sAcc[tid+192]) / sSum;
    __syncthreads();

    if (w < CCH) {
        float p = 0.f;
#pragma unroll
        for (int r = 0; r < 4; r++) {
            int k = lane + r*32;
            float v = (k < 64) ? sXout[k] : sXde[k-64];
            p += v * faW[k*CCH + w];
        }
#pragma unroll
        for (int o = 16; o; o >>= 1) p += __shfl_down_sync(0xffffffffu, p, o);
        if (lane == 0) {
            float o2 = p + faB[w];
            out[(size_t)i*CCH + w] = o2 > 0.f ? o2 : expm1f(o2);
        }
    }
}

// ---------------- launch ----------------
extern "C" void kernel_launch(void* const* d_in, const int* in_sizes, int n_in,
                              void* d_out, int out_size)
{
    const float* x      = (const float*)d_in[0];   // [5, 31744, 5]
    const int*   ei     = (const int*)  d_in[1];   // [5, 2, 507904]
    // d_in[2] = batch (unused; graphs are 62 contiguous nodes)
    const float* de     = (const float*)d_in[3];   // [512, 930]
    const float* bn_g   = (const float*)d_in[4];
    const float* bn_b   = (const float*)d_in[5];
    const float* W      = (const float*)d_in[6];
    const float* asrc   = (const float*)d_in[7];
    const float* adst   = (const float*)d_in[8];
    const float* gbias  = (const float*)d_in[9];
    const float* fgW    = (const float*)d_in[10];
    const float* fgB    = (const float*)d_in[11];
    const float* lng    = (const float*)d_in[12];
    const float* lnb    = (const float*)d_in[13];
    const float* qW     = (const float*)d_in[14];
    const float* qb     = (const float*)d_in[15];
    const float* kW     = (const float*)d_in[16];
    const float* kb     = (const float*)d_in[17];
    const float* vW     = (const float*)d_in[18];
    const float* vb     = (const float*)d_in[19];
    const float* faW    = (const float*)d_in[20];
    const float* faB    = (const float*)d_in[21];
    float* out = (float*)d_out;

    bn_partial_kernel<<<dim3(NBNBLK, NBANDS), 256>>>(x);
    bn_finalize_kernel<<<1, 32>>>(bn_g, bn_b);
    gat_kernel<<<dim3(BGRAPH, NBANDS), 512>>>(x, ei, W, asrc, adst, gbias);
    ln_stats_kernel<<<BGRAPH, 256>>>(de);
    qkv_gemm_kernel<<<dim3(32, 3), 256>>>(de, lng, lnb, qW, qb, kW, kb, vW, vb);
    attn_kernel<<<BGRAPH, 256>>>(fgW, fgB, faW, faB, out);
}